// round 9
// baseline (speedup 1.0000x reference)
#include <cuda_runtime.h>
#include <cuda_fp16.h>
#include <cstdint>

// Problem constants
#define B_  4
#define T_  2048
#define C_  1024
#define H_  16
#define DH_ 64
#define M_ROWS (B_ * T_)      // 8192
#define QKV_N  (3 * C_)       // 3072
#define K_DIM  1024

// ---------------------------------------------------------------------------
// Device scratch
// ---------------------------------------------------------------------------
__device__ float g_qkv[(size_t)M_ROWS * QKV_N];        // 96 MB fp32 (QKV GEMM out)
__device__ __half g_ah[(size_t)M_ROWS * K_DIM];        // A hi (x, later O)
__device__ __half g_al[(size_t)M_ROWS * K_DIM];        // A lo
__device__ __half g_wqh[(size_t)QKV_N * K_DIM];        // W_qkv^T hi
__device__ __half g_wql[(size_t)QKV_N * K_DIM];
__device__ __half g_woh[(size_t)C_ * K_DIM];           // W_out^T hi
__device__ __half g_wol[(size_t)C_ * K_DIM];
// per-head fp16 hi/lo: q,k as [bh][T][64]; v transposed [bh][64][T]
__device__ __half g_qh[(size_t)B_ * H_ * T_ * DH_];
__device__ __half g_ql[(size_t)B_ * H_ * T_ * DH_];
__device__ __half g_kh[(size_t)B_ * H_ * T_ * DH_];
__device__ __half g_kl[(size_t)B_ * H_ * T_ * DH_];
__device__ __half g_vth[(size_t)B_ * H_ * DH_ * T_];
__device__ __half g_vtl[(size_t)B_ * H_ * DH_ * T_];

// ---------------------------------------------------------------------------
// Portable PTX helpers
// ---------------------------------------------------------------------------
__device__ __forceinline__ uint32_t smem_u32(const void* p) {
    uint32_t a;
    asm("{ .reg .u64 t; cvta.to.shared.u64 t, %1; cvt.u32.u64 %0, t; }" : "=r"(a) : "l"(p));
    return a;
}
#define CP_ASYNC16(dst, src) \
    asm volatile("cp.async.cg.shared.global [%0], [%1], 16;" :: "r"(dst), "l"(src))
#define CP_COMMIT() asm volatile("cp.async.commit_group;" ::: "memory")
#define CP_WAIT2()  asm volatile("cp.async.wait_group 2;" ::: "memory")
#define CP_WAIT1()  asm volatile("cp.async.wait_group 1;" ::: "memory")
#define CP_WAIT0()  asm volatile("cp.async.wait_group 0;" ::: "memory")
#define LDSM4(r0, r1, r2, r3, addr) \
    asm volatile("ldmatrix.sync.aligned.m8n8.x4.shared.b16 {%0,%1,%2,%3}, [%4];" \
                 : "=r"(r0), "=r"(r1), "=r"(r2), "=r"(r3) : "r"(addr))

__device__ __forceinline__ void mma16816(float* c, const uint32_t* a, const uint32_t* b) {
    asm volatile(
        "mma.sync.aligned.m16n8k16.row.col.f32.f16.f16.f32 "
        "{%0,%1,%2,%3},{%4,%5,%6,%7},{%8,%9},{%0,%1,%2,%3};"
        : "+f"(c[0]), "+f"(c[1]), "+f"(c[2]), "+f"(c[3])
        : "r"(a[0]), "r"(a[1]), "r"(a[2]), "r"(a[3]), "r"(b[0]), "r"(b[1]));
}

// Swizzle for 64B-row tiles (GEMM: [128 rows x 4 chunks])
__device__ __forceinline__ uint32_t sw_off(int r, int c) {
    return (uint32_t)((r << 2) | (c ^ ((r >> 1) & 3))) << 4;
}
// Swizzle for 128B-row tiles (attention: [64 rows x 8 chunks])
__device__ __forceinline__ uint32_t swk(int r, int c) {
    return (uint32_t)((r << 3) | (c ^ (r & 7))) << 4;
}
__device__ __forceinline__ uint32_t pack_h2(__half a, __half b) {
    __half2 h = __halves2half2(a, b);
    return *(uint32_t*)&h;
}

// ---------------------------------------------------------------------------
// Split-conversion kernels
// ---------------------------------------------------------------------------
__global__ __launch_bounds__(256)
void conv_split(const float4* __restrict__ src, __half2* __restrict__ hi,
                __half2* __restrict__ lo)
{
    const int i = blockIdx.x * 256 + threadIdx.x;
    float4 v = src[i];
    __half h0 = __float2half_rn(v.x), h1 = __float2half_rn(v.y);
    __half h2 = __float2half_rn(v.z), h3 = __float2half_rn(v.w);
    __half l0 = __float2half_rn(v.x - __half2float(h0));
    __half l1 = __float2half_rn(v.y - __half2float(h1));
    __half l2 = __float2half_rn(v.z - __half2float(h2));
    __half l3 = __float2half_rn(v.w - __half2float(h3));
    hi[2 * i]     = __halves2half2(h0, h1);
    hi[2 * i + 1] = __halves2half2(h2, h3);
    lo[2 * i]     = __halves2half2(l0, l1);
    lo[2 * i + 1] = __halves2half2(l2, l3);
}

__global__ __launch_bounds__(256)
void transpose_split(const float* __restrict__ W, __half* __restrict__ Th,
                     __half* __restrict__ Tl, int K, int N)
{
    __shared__ float tile[32][33];
    const int n0 = blockIdx.x * 32, k0 = blockIdx.y * 32;
    const int tx = threadIdx.x & 31, ty = threadIdx.x >> 5;
#pragma unroll
    for (int j = 0; j < 32; j += 8)
        tile[ty + j][tx] = W[(size_t)(k0 + ty + j) * N + n0 + tx];
    __syncthreads();
#pragma unroll
    for (int j = 0; j < 32; j += 8) {
        float v = tile[tx][ty + j];
        __half h = __float2half_rn(v);
        __half l = __float2half_rn(v - __half2float(h));
        size_t o = (size_t)(n0 + ty + j) * K + k0 + tx;
        Th[o] = h; Tl[o] = l;
    }
}

// ---------------------------------------------------------------------------
// HMMA split-fp16 GEMM — 3-stage cp.async pipeline.
// ---------------------------------------------------------------------------
#define STG_BYTES 32768
#define HG_DYN    (3 * STG_BYTES)

__device__ __forceinline__ void load_stage(
    const __half* __restrict__ Ah, const __half* __restrict__ Al,
    const __half* __restrict__ Bh, const __half* __restrict__ Bl,
    int bm, int bn, int k0, uint32_t sbase, int tid)
{
#pragma unroll
    for (int i = 0; i < 2; i++) {
        const int idx = tid + i * 256;
        const int r = idx >> 2;
        const int c = idx & 3;
        const uint32_t so = sw_off(r, c);
        const size_t goA = (size_t)(bm + r) * K_DIM + k0 + c * 8;
        const size_t goB = (size_t)(bn + r) * K_DIM + k0 + c * 8;
        CP_ASYNC16(sbase +          so, Ah + goA);
        CP_ASYNC16(sbase + 8192u  + so, Al + goA);
        CP_ASYNC16(sbase + 16384u + so, Bh + goB);
        CP_ASYNC16(sbase + 24576u + so, Bl + goB);
    }
}

__global__ __launch_bounds__(256, 2)
void hmma_gemm(const __half* __restrict__ Ah, const __half* __restrict__ Al,
               const __half* __restrict__ Bh, const __half* __restrict__ Bl,
               float* __restrict__ C, int N)
{
    extern __shared__ __align__(16) char sm_raw[];
    const int tid  = threadIdx.x;
    const int lane = tid & 31;
    const int wid  = tid >> 5;
    const int wr   = wid & 3;
    const int wc   = wid >> 2;
    const int bm = blockIdx.y * 128, bn = blockIdx.x * 128;
    const uint32_t s0 = smem_u32(sm_raw);

    float acc[2][8][4];
#pragma unroll
    for (int i = 0; i < 2; i++)
#pragma unroll
        for (int j = 0; j < 8; j++)
#pragma unroll
            for (int q = 0; q < 4; q++) acc[i][j][q] = 0.f;

    const int rA_base = wr * 32 + ((lane >> 3) & 1) * 8 + (lane & 7);
    const int cA_half = lane >> 4;
    const int rB_base = wc * 64 + ((lane >> 4) ? 8 : 0) + (lane & 7);
    const int cB_half = (lane >> 3) & 1;

    constexpr int NIT = K_DIM / 32;   // 32
    // Prologue: 2 stages in flight
    load_stage(Ah, Al, Bh, Bl, bm, bn, 0, s0, tid);
    CP_COMMIT();
    load_stage(Ah, Al, Bh, Bl, bm, bn, 32, s0 + STG_BYTES, tid);
    CP_COMMIT();

    for (int it = 0; it < NIT; it++) {
        if (it + 2 < NIT) {
            load_stage(Ah, Al, Bh, Bl, bm, bn, (it + 2) * 32,
                       s0 + (uint32_t)(((it + 2) % 3) * STG_BYTES), tid);
            CP_COMMIT();
        }
        const int rem = NIT - 1 - it;
        if (rem >= 2) CP_WAIT2(); else if (rem == 1) CP_WAIT1(); else CP_WAIT0();
        __syncthreads();

        const uint32_t sa = s0 + (uint32_t)((it % 3) * STG_BYTES);
#pragma unroll
        for (int s = 0; s < 2; s++) {
            uint32_t afh[2][4], afl[2][4], bfh[8][2], bfl[8][2];
            const int cA = s * 2 + cA_half;
            const int cB = s * 2 + cB_half;
#pragma unroll
            for (int mt = 0; mt < 2; mt++) {
                const uint32_t oa = sw_off(rA_base + mt * 16, cA);
                LDSM4(afh[mt][0], afh[mt][1], afh[mt][2], afh[mt][3], sa + oa);
                LDSM4(afl[mt][0], afl[mt][1], afl[mt][2], afl[mt][3], sa + 8192u + oa);
            }
#pragma unroll
            for (int np = 0; np < 4; np++) {
                const uint32_t ob = sw_off(rB_base + np * 16, cB);
                uint32_t t0, t1, t2, t3;
                LDSM4(t0, t1, t2, t3, sa + 16384u + ob);
                bfh[np * 2][0] = t0; bfh[np * 2][1] = t1;
                bfh[np * 2 + 1][0] = t2; bfh[np * 2 + 1][1] = t3;
                LDSM4(t0, t1, t2, t3, sa + 24576u + ob);
                bfl[np * 2][0] = t0; bfl[np * 2][1] = t1;
                bfl[np * 2 + 1][0] = t2; bfl[np * 2 + 1][1] = t3;
            }
#pragma unroll
            for (int mt = 0; mt < 2; mt++)
#pragma unroll
                for (int nt = 0; nt < 8; nt++) {
                    mma16816(acc[mt][nt], afh[mt], bfh[nt]);
                    mma16816(acc[mt][nt], afh[mt], bfl[nt]);
                    mma16816(acc[mt][nt], afl[mt], bfh[nt]);
                }
        }
        __syncthreads();
    }

#pragma unroll
    for (int mt = 0; mt < 2; mt++) {
        const int row = bm + wr * 32 + mt * 16 + (lane >> 2);
#pragma unroll
        for (int nt = 0; nt < 8; nt++) {
            const int col = bn + wc * 64 + nt * 8 + (lane & 3) * 2;
            float* p = C + (size_t)row * N + col;
            float2 v0; v0.x = acc[mt][nt][0]; v0.y = acc[mt][nt][1];
            float2 v1; v1.x = acc[mt][nt][2]; v1.y = acc[mt][nt][3];
            *(float2*)p = v0;
            *(float2*)(p + (size_t)8 * N) = v1;
        }
    }
}

// ---------------------------------------------------------------------------
// prep_qkv (unchanged, known-good)
// ---------------------------------------------------------------------------
__device__ __forceinline__ void split8_store(const float* v, float scale,
                                             __half* dh, __half* dl)
{
    __half th[8], tl[8];
#pragma unroll
    for (int i = 0; i < 8; i++) {
        float x = v[i] * scale;
        __half h = __float2half_rn(x);
        th[i] = h;
        tl[i] = __float2half_rn(x - __half2float(h));
    }
    *(uint4*)dh = *(uint4*)th;
    *(uint4*)dl = *(uint4*)tl;
}

__global__ __launch_bounds__(256)
void prep_qkv(const float* __restrict__ qkv,
              __half* __restrict__ qh, __half* __restrict__ ql,
              __half* __restrict__ kh, __half* __restrict__ kl,
              __half* __restrict__ vth, __half* __restrict__ vtl)
{
    __shared__ __half svh[64][33];
    __shared__ __half svl[64][33];
    const int bh = blockIdx.y, b = bh >> 4, h = bh & 15;
    const int t0 = blockIdx.x * 32;
    const int tl_ = threadIdx.x >> 3;
    const int d0  = (threadIdx.x & 7) * 8;
    const float* src = qkv + (size_t)(b * T_ + t0 + tl_) * QKV_N + h * 64 + d0;
    const size_t qo = (size_t)(bh * T_ + t0 + tl_) * 64 + d0;

    float vbuf[8];
    *(float4*)(vbuf)     = *(const float4*)(src);
    *(float4*)(vbuf + 4) = *(const float4*)(src + 4);
    split8_store(vbuf, 0.125f, qh + qo, ql + qo);
    *(float4*)(vbuf)     = *(const float4*)(src + 1024);
    *(float4*)(vbuf + 4) = *(const float4*)(src + 1028);
    split8_store(vbuf, 1.0f, kh + qo, kl + qo);
    *(float4*)(vbuf)     = *(const float4*)(src + 2048);
    *(float4*)(vbuf + 4) = *(const float4*)(src + 2052);
#pragma unroll
    for (int j = 0; j < 8; j++) {
        __half h16 = __float2half_rn(vbuf[j]);
        svh[d0 + j][tl_] = h16;
        svl[d0 + j][tl_] = __float2half_rn(vbuf[j] - __half2float(h16));
    }
    __syncthreads();
#pragma unroll
    for (int j = 0; j < 4; j++) {
        const int idx = threadIdx.x + j * 256;
        const int d = idx >> 4, tp = idx & 15;
        __half2 hv = __halves2half2(svh[d][2 * tp], svh[d][2 * tp + 1]);
        __half2 lv = __halves2half2(svl[d][2 * tp], svl[d][2 * tp + 1]);
        const size_t o = ((size_t)(bh * 64 + d) * T_ + t0 + 2 * tp) >> 1;
        ((__half2*)vth)[o] = hv;
        ((__half2*)vtl)[o] = lv;
    }
}

// ---------------------------------------------------------------------------
// HMMA causal flash attention — 3-stage cp.async pipeline.
// ---------------------------------------------------------------------------
#define ATT_STG 32768
#define ATT_DYN (3 * ATT_STG + 1024)

__device__ __forceinline__ void attn_load_stage(
    const __half* __restrict__ kh, const __half* __restrict__ kl,
    const __half* __restrict__ vh, const __half* __restrict__ vl,
    size_t kbase, size_t vbase, int kv0, uint32_t sb, int tid)
{
#pragma unroll
    for (int j = 0; j < 2; j++) {
        const int idx = tid + j * 256;
        const int r = idx >> 3, c = idx & 7;
        const uint32_t so = swk(r, c);
        const size_t ko = kbase + (size_t)(kv0 + r) * 64 + c * 8;
        const size_t vo = vbase + (size_t)r * T_ + kv0 + c * 8;
        CP_ASYNC16(sb +          so, kh + ko);
        CP_ASYNC16(sb + 8192u  + so, kl + ko);
        CP_ASYNC16(sb + 16384u + so, vh + vo);
        CP_ASYNC16(sb + 24576u + so, vl + vo);
    }
}

__global__ __launch_bounds__(256, 2)
void attn_mma(const __half* __restrict__ qh_g, const __half* __restrict__ ql_g,
              const __half* __restrict__ kh_g, const __half* __restrict__ kl_g,
              const __half* __restrict__ vh_g, const __half* __restrict__ vl_g,
              __half* __restrict__ oh_g, __half* __restrict__ ol_g)
{
    extern __shared__ __align__(16) char smraw[];
    const uint32_t s0r = smem_u32(smraw);
    const uint32_t s0  = (s0r + 1023u) & ~1023u;

    const int tid = threadIdx.x, lane = tid & 31, w = tid >> 5;
    const int qb = blockIdx.x, bh = blockIdx.y;
    const int b = bh >> 4, h = bh & 15;
    const int qw  = qb * 128 + w * 16;
    const int qr0 = qw + (lane >> 2);

    uint32_t qfh[4][4], qfl[4][4];
    {
        const size_t base = (size_t)bh * T_ * 64;
        const __half* qp = qh_g + base;
        const __half* lp = ql_g + base;
        const int klo = (lane & 3) << 1;
        const size_t r0o = (size_t)qr0 * 64, r1o = (size_t)(qr0 + 8) * 64;
#pragma unroll
        for (int kd = 0; kd < 4; kd++) {
            const int kk = kd * 16 + klo;
            qfh[kd][0] = *(const uint32_t*)(qp + r0o + kk);
            qfh[kd][1] = *(const uint32_t*)(qp + r1o + kk);
            qfh[kd][2] = *(const uint32_t*)(qp + r0o + kk + 8);
            qfh[kd][3] = *(const uint32_t*)(qp + r1o + kk + 8);
            qfl[kd][0] = *(const uint32_t*)(lp + r0o + kk);
            qfl[kd][1] = *(const uint32_t*)(lp + r1o + kk);
            qfl[kd][2] = *(const uint32_t*)(lp + r0o + kk + 8);
            qfl[kd][3] = *(const uint32_t*)(lp + r1o + kk + 8);
        }
    }

    float accO[8][4];
#pragma unroll
    for (int i = 0; i < 8; i++)
#pragma unroll
        for (int j = 0; j < 4; j++) accO[i][j] = 0.f;
    float m0 = -1e30f, m1 = -1e30f, l0 = 0.f, l1 = 0.f;

    const size_t kbase = (size_t)bh * T_ * 64;
    const size_t vbase = (size_t)bh * 64 * T_;
    const int ntk = 2 * (qb + 1);

    const int bRow = ((lane >> 4) << 3) | (lane & 7);
    const int bSel = (lane >> 3) & 1;

    // Prologue: 2 stages in flight (ntk >= 2 always)
    attn_load_stage(kh_g, kl_g, vh_g, vl_g, kbase, vbase, 0, s0, tid);
    CP_COMMIT();
    attn_load_stage(kh_g, kl_g, vh_g, vl_g, kbase, vbase, 64, s0 + ATT_STG, tid);
    CP_COMMIT();

    for (int t = 0; t < ntk; t++) {
        if (t + 2 < ntk) {
            attn_load_stage(kh_g, kl_g, vh_g, vl_g, kbase, vbase, (t + 2) * 64,
                            s0 + (uint32_t)(((t + 2) % 3) * ATT_STG), tid);
            CP_COMMIT();
        }
        const int rem = ntk - 1 - t;
        if (rem >= 2) CP_WAIT2(); else if (rem == 1) CP_WAIT1(); else CP_WAIT0();
        __syncthreads();

        const uint32_t sb = s0 + (uint32_t)((t % 3) * ATT_STG);
        const int kv0 = t * 64;

        if (kv0 <= qw + 15) {
            // ---- S = Q K^T (split x3) ----
            float s[8][4];
#pragma unroll
            for (int i = 0; i < 8; i++)
#pragma unroll
                for (int j = 0; j < 4; j++) s[i][j] = 0.f;

#pragma unroll
            for (int kd = 0; kd < 4; kd++) {
#pragma unroll
                for (int np = 0; np < 4; np++) {
                    const uint32_t off = swk(np * 16 + bRow, kd * 2 + bSel);
                    uint32_t b0, b1, b2, b3, c0, c1, c2, c3;
                    LDSM4(b0, b1, b2, b3, sb + off);
                    LDSM4(c0, c1, c2, c3, sb + 8192u + off);
                    uint32_t Bh0[2] = {b0, b1}, Bh1[2] = {b2, b3};
                    uint32_t Bl0[2] = {c0, c1}, Bl1[2] = {c2, c3};
                    mma16816(s[2 * np],     qfh[kd], Bh0);
                    mma16816(s[2 * np],     qfl[kd], Bh0);
                    mma16816(s[2 * np],     qfh[kd], Bl0);
                    mma16816(s[2 * np + 1], qfh[kd], Bh1);
                    mma16816(s[2 * np + 1], qfl[kd], Bh1);
                    mma16816(s[2 * np + 1], qfh[kd], Bl1);
                }
            }

            // ---- causal mask ----
            if (kv0 + 63 > qw) {
#pragma unroll
                for (int nt = 0; nt < 8; nt++) {
                    const int col = kv0 + nt * 8 + ((lane & 3) << 1);
                    if (col     > qr0)     s[nt][0] = -1e30f;
                    if (col + 1 > qr0)     s[nt][1] = -1e30f;
                    if (col     > qr0 + 8) s[nt][2] = -1e30f;
                    if (col + 1 > qr0 + 8) s[nt][3] = -1e30f;
                }
            }

            // ---- online softmax ----
            float mx0 = -1e30f, mx1 = -1e30f;
#pragma unroll
            for (int nt = 0; nt < 8; nt++) {
                mx0 = fmaxf(mx0, fmaxf(s[nt][0], s[nt][1]));
                mx1 = fmaxf(mx1, fmaxf(s[nt][2], s[nt][3]));
            }
            mx0 = fmaxf(mx0, __shfl_xor_sync(0xffffffffu, mx0, 1));
            mx0 = fmaxf(mx0, __shfl_xor_sync(0xffffffffu, mx0, 2));
            mx1 = fmaxf(mx1, __shfl_xor_sync(0xffffffffu, mx1, 1));
            mx1 = fmaxf(mx1, __shfl_xor_sync(0xffffffffu, mx1, 2));
            const float mn0 = fmaxf(m0, mx0), mn1 = fmaxf(m1, mx1);
            const float a0 = __expf(m0 - mn0), a1 = __expf(m1 - mn1);
            m0 = mn0; m1 = mn1;
            l0 *= a0;  l1 *= a1;
#pragma unroll
            for (int nt = 0; nt < 8; nt++) {
                accO[nt][0] *= a0; accO[nt][1] *= a0;
                accO[nt][2] *= a1; accO[nt][3] *= a1;
            }

            uint32_t ph[4][4], pl[4][4];
            float sum0 = 0.f, sum1 = 0.f;
#pragma unroll
            for (int nt = 0; nt < 8; nt++) {
                const float p0 = __expf(s[nt][0] - m0);
                const float p1 = __expf(s[nt][1] - m0);
                const float p2 = __expf(s[nt][2] - m1);
                const float p3 = __expf(s[nt][3] - m1);
                sum0 += p0 + p1; sum1 += p2 + p3;
                const __half h0 = __float2half_rn(p0), h1 = __float2half_rn(p1);
                const __half h2 = __float2half_rn(p2), h3 = __float2half_rn(p3);
                const int kt = nt >> 1, rg = (nt & 1) * 2;
                ph[kt][rg]     = pack_h2(h0, h1);
                ph[kt][rg + 1] = pack_h2(h2, h3);
                pl[kt][rg]     = pack_h2(__float2half_rn(p0 - __half2float(h0)),
                                         __float2half_rn(p1 - __half2float(h1)));
                pl[kt][rg + 1] = pack_h2(__float2half_rn(p2 - __half2float(h2)),
                                         __float2half_rn(p3 - __half2float(h3)));
            }
            sum0 += __shfl_xor_sync(0xffffffffu, sum0, 1);
            sum0 += __shfl_xor_sync(0xffffffffu, sum0, 2);
            sum1 += __shfl_xor_sync(0xffffffffu, sum1, 1);
            sum1 += __shfl_xor_sync(0xffffffffu, sum1, 2);
            l0 += sum0; l1 += sum1;

            // ---- O += P V (split x3) ----
#pragma unroll
            for (int kt = 0; kt < 4; kt++) {
#pragma unroll
                for (int np = 0; np < 4; np++) {
                    const uint32_t off = swk(np * 16 + bRow, kt * 2 + bSel);
                    uint32_t v0, v1, v2, v3, u0, u1, u2, u3;
                    LDSM4(v0, v1, v2, v3, sb + 16384u + off);
                    LDSM4(u0, u1, u2, u3, sb + 24576u + off);
                    uint32_t Vh0[2] = {v0, v1}, Vh1[2] = {v2, v3};
                    uint32_t Vl0[2] = {u0, u1}, Vl1[2] = {u2, u3};
                    mma16816(accO[2 * np],     ph[kt], Vh0);
                    mma16816(accO[2 * np],     pl[kt], Vh0);
                    mma16816(accO[2 * np],     ph[kt], Vl0);
                    mma16816(accO[2 * np + 1], ph[kt], Vh1);
                    mma16816(accO[2 * np + 1], pl[kt], Vh1);
                    mma16816(accO[2 * np + 1], ph[kt], Vl1);
                }
            }
        }
        __syncthreads();
    }

    // ---- epilogue ----
    const float inv0 = 1.f / l0, inv1 = 1.f / l1;
    const size_t row0 = (size_t)(b * T_ + qr0) * C_ + h * 64;
    const size_t row1 = (size_t)(b * T_ + qr0 + 8) * C_ + h * 64;
#pragma unroll
    for (int nt = 0; nt < 8; nt++) {
        const int col = nt * 8 + ((lane & 3) << 1);
        const float o0 = accO[nt][0] * inv0, o1 = accO[nt][1] * inv0;
        const float o2 = accO[nt][2] * inv1, o3 = accO[nt][3] * inv1;
        const __half h0 = __float2half_rn(o0), h1 = __float2half_rn(o1);
        const __half h2 = __float2half_rn(o2), h3 = __float2half_rn(o3);
        *(uint32_t*)(oh_g + row0 + col) = pack_h2(h0, h1);
        *(uint32_t*)(ol_g + row0 + col) = pack_h2(__float2half_rn(o0 - __half2float(h0)),
                                                  __float2half_rn(o1 - __half2float(h1)));
        *(uint32_t*)(oh_g + row1 + col) = pack_h2(h2, h3);
        *(uint32_t*)(ol_g + row1 + col) = pack_h2(__float2half_rn(o2 - __half2float(h2)),
                                                  __float2half_rn(o3 - __half2float(h3)));
    }
}

// ---------------------------------------------------------------------------
// kernel_launch
// ---------------------------------------------------------------------------
extern "C" void kernel_launch(void* const* d_in, const int* in_sizes, int n_in,
                              void* d_out, int out_size)
{
    (void)in_sizes; (void)n_in; (void)out_size;
    const float* x    = (const float*)d_in[0];
    const float* Wqkv = (const float*)d_in[1];
    const float* Wout = (const float*)d_in[2];
    float* out = (float*)d_out;

    float* qkv;
    __half *ah, *al, *wqh, *wql, *woh, *wol, *qh, *ql, *kh, *kl, *vth, *vtl;
    cudaGetSymbolAddress((void**)&qkv, g_qkv);
    cudaGetSymbolAddress((void**)&ah,  g_ah);
    cudaGetSymbolAddress((void**)&al,  g_al);
    cudaGetSymbolAddress((void**)&wqh, g_wqh);
    cudaGetSymbolAddress((void**)&wql, g_wql);
    cudaGetSymbolAddress((void**)&woh, g_woh);
    cudaGetSymbolAddress((void**)&wol, g_wol);
    cudaGetSymbolAddress((void**)&qh,  g_qh);
    cudaGetSymbolAddress((void**)&ql,  g_ql);
    cudaGetSymbolAddress((void**)&kh,  g_kh);
    cudaGetSymbolAddress((void**)&kl,  g_kl);
    cudaGetSymbolAddress((void**)&vth, g_vth);
    cudaGetSymbolAddress((void**)&vtl, g_vtl);

    cudaFuncSetAttribute(hmma_gemm, cudaFuncAttributeMaxDynamicSharedMemorySize, HG_DYN);
    cudaFuncSetAttribute(attn_mma,  cudaFuncAttributeMaxDynamicSharedMemorySize, ATT_DYN);

    const int n_elems4 = (M_ROWS * K_DIM) / 4;

    // 0) Split-convert x and transposed weights to fp16 hi/lo
    conv_split<<<n_elems4 / 256, 256>>>((const float4*)x, (__half2*)ah, (__half2*)al);
    transpose_split<<<dim3(QKV_N / 32, K_DIM / 32), 256>>>(Wqkv, wqh, wql, K_DIM, QKV_N);
    transpose_split<<<dim3(C_ / 32, K_DIM / 32), 256>>>(Wout, woh, wol, K_DIM, C_);

    // 1) QKV projection (HMMA split-fp16, 3-stage pipeline)
    hmma_gemm<<<dim3(QKV_N / 128, M_ROWS / 128), 256, HG_DYN>>>(ah, al, wqh, wql, qkv, QKV_N);

    // 2) Split per-head Q/K/V to fp16 hi/lo (V transposed), Q pre-scaled
    prep_qkv<<<dim3(T_ / 32, B_ * H_), 256>>>(qkv, qh, ql, kh, kl, vth, vtl);

    // 3) Causal attention on tensor cores; O written as fp16 hi/lo into ah/al
    attn_mma<<<dim3(T_ / 128, B_ * H_), 256, ATT_DYN>>>(qh, ql, kh, kl, vth, vtl, ah, al);

    // 4) Output projection (HMMA split-fp16, 3-stage pipeline)
    hmma_gemm<<<dim3(C_ / 128, M_ROWS / 128), 256, HG_DYN>>>(ah, al, woh, wol, out, C_);
}

// round 11
// speedup vs baseline: 1.4864x; 1.4864x over previous
#include <cuda_runtime.h>
#include <cuda_fp16.h>
#include <cstdint>

// Problem constants
#define B_  4
#define T_  2048
#define C_  1024
#define H_  16
#define DH_ 64
#define M_ROWS (B_ * T_)      // 8192
#define QKV_N  (3 * C_)       // 3072
#define K_DIM  1024

// ---------------------------------------------------------------------------
// Device scratch
// ---------------------------------------------------------------------------
__device__ __half g_ah[(size_t)M_ROWS * K_DIM];        // A hi (x, later O)
__device__ __half g_al[(size_t)M_ROWS * K_DIM];        // A lo
__device__ __half g_wqh[(size_t)QKV_N * K_DIM];        // W_qkv^T hi
__device__ __half g_wql[(size_t)QKV_N * K_DIM];
__device__ __half g_woh[(size_t)C_ * K_DIM];           // W_out^T hi
__device__ __half g_wol[(size_t)C_ * K_DIM];
// per-head fp16 hi/lo: q,k as [bh][T][64]; v transposed [bh][64][T]
__device__ __half g_qh[(size_t)B_ * H_ * T_ * DH_];
__device__ __half g_ql[(size_t)B_ * H_ * T_ * DH_];
__device__ __half g_kh[(size_t)B_ * H_ * T_ * DH_];
__device__ __half g_kl[(size_t)B_ * H_ * T_ * DH_];
__device__ __half g_vth[(size_t)B_ * H_ * DH_ * T_];
__device__ __half g_vtl[(size_t)B_ * H_ * DH_ * T_];

// ---------------------------------------------------------------------------
// Portable PTX helpers
// ---------------------------------------------------------------------------
__device__ __forceinline__ uint32_t smem_u32(const void* p) {
    uint32_t a;
    asm("{ .reg .u64 t; cvta.to.shared.u64 t, %1; cvt.u32.u64 %0, t; }" : "=r"(a) : "l"(p));
    return a;
}
#define CP_ASYNC16(dst, src) \
    asm volatile("cp.async.cg.shared.global [%0], [%1], 16;" :: "r"(dst), "l"(src))
#define CP_COMMIT() asm volatile("cp.async.commit_group;" ::: "memory")
#define CP_WAIT1()  asm volatile("cp.async.wait_group 1;" ::: "memory")
#define CP_WAIT0()  asm volatile("cp.async.wait_group 0;" ::: "memory")
#define LDSM4(r0, r1, r2, r3, addr) \
    asm volatile("ldmatrix.sync.aligned.m8n8.x4.shared.b16 {%0,%1,%2,%3}, [%4];" \
                 : "=r"(r0), "=r"(r1), "=r"(r2), "=r"(r3) : "r"(addr))

__device__ __forceinline__ void mma16816(float* c, const uint32_t* a, const uint32_t* b) {
    asm volatile(
        "mma.sync.aligned.m16n8k16.row.col.f32.f16.f16.f32 "
        "{%0,%1,%2,%3},{%4,%5,%6,%7},{%8,%9},{%0,%1,%2,%3};"
        : "+f"(c[0]), "+f"(c[1]), "+f"(c[2]), "+f"(c[3])
        : "r"(a[0]), "r"(a[1]), "r"(a[2]), "r"(a[3]), "r"(b[0]), "r"(b[1]));
}

// Swizzle for 64B-row tiles (GEMM: [128 rows x 4 chunks])
__device__ __forceinline__ uint32_t sw_off(int r, int c) {
    return (uint32_t)((r << 2) | (c ^ ((r >> 1) & 3))) << 4;
}
// Swizzle for 128B-row tiles (attention: [64 rows x 8 chunks])
__device__ __forceinline__ uint32_t swk(int r, int c) {
    return (uint32_t)((r << 3) | (c ^ (r & 7))) << 4;
}
__device__ __forceinline__ uint32_t pack_h2(__half a, __half b) {
    __half2 h = __halves2half2(a, b);
    return *(uint32_t*)&h;
}

// ---------------------------------------------------------------------------
// Split-conversion kernels
// ---------------------------------------------------------------------------
__global__ __launch_bounds__(256)
void conv_split(const float4* __restrict__ src, __half2* __restrict__ hi,
                __half2* __restrict__ lo)
{
    const int i = blockIdx.x * 256 + threadIdx.x;
    float4 v = src[i];
    __half h0 = __float2half_rn(v.x), h1 = __float2half_rn(v.y);
    __half h2 = __float2half_rn(v.z), h3 = __float2half_rn(v.w);
    __half l0 = __float2half_rn(v.x - __half2float(h0));
    __half l1 = __float2half_rn(v.y - __half2float(h1));
    __half l2 = __float2half_rn(v.z - __half2float(h2));
    __half l3 = __float2half_rn(v.w - __half2float(h3));
    hi[2 * i]     = __halves2half2(h0, h1);
    hi[2 * i + 1] = __halves2half2(h2, h3);
    lo[2 * i]     = __halves2half2(l0, l1);
    lo[2 * i + 1] = __halves2half2(l2, l3);
}

__global__ __launch_bounds__(256)
void transpose_split(const float* __restrict__ W, __half* __restrict__ Th,
                     __half* __restrict__ Tl, int K, int N)
{
    __shared__ float tile[32][33];
    const int n0 = blockIdx.x * 32, k0 = blockIdx.y * 32;
    const int tx = threadIdx.x & 31, ty = threadIdx.x >> 5;
#pragma unroll
    for (int j = 0; j < 32; j += 8)
        tile[ty + j][tx] = W[(size_t)(k0 + ty + j) * N + n0 + tx];
    __syncthreads();
#pragma unroll
    for (int j = 0; j < 32; j += 8) {
        float v = tile[tx][ty + j];
        __half h = __float2half_rn(v);
        __half l = __float2half_rn(v - __half2float(h));
        size_t o = (size_t)(n0 + ty + j) * K + k0 + tx;
        Th[o] = h; Tl[o] = l;
    }
}

// ---------------------------------------------------------------------------
// HMMA split-fp16 GEMM — R8 2-stage pipeline (known good), templated epilogue.
// MODE 0: plain fp32 C.  MODE 1: fused QKV epilogue -> per-head fp16 hi/lo
//   (Q scaled 1/8, K plain, V transposed via smem staging).
// ---------------------------------------------------------------------------
#define STG_BYTES 32768
#define HG_DYN    (2 * STG_BYTES)

__device__ __forceinline__ void load_stage(
    const __half* __restrict__ Ah, const __half* __restrict__ Al,
    const __half* __restrict__ Bh, const __half* __restrict__ Bl,
    int bm, int bn, int k0, uint32_t sbase, int tid)
{
#pragma unroll
    for (int i = 0; i < 2; i++) {
        const int idx = tid + i * 256;
        const int r = idx >> 2;
        const int c = idx & 3;
        const uint32_t so = sw_off(r, c);
        const size_t goA = (size_t)(bm + r) * K_DIM + k0 + c * 8;
        const size_t goB = (size_t)(bn + r) * K_DIM + k0 + c * 8;
        CP_ASYNC16(sbase +          so, Ah + goA);
        CP_ASYNC16(sbase + 8192u  + so, Al + goA);
        CP_ASYNC16(sbase + 16384u + so, Bh + goB);
        CP_ASYNC16(sbase + 24576u + so, Bl + goB);
    }
}

template<int MODE>
__global__ __launch_bounds__(256)
void hmma_gemm_t(const __half* __restrict__ Ah, const __half* __restrict__ Al,
                 const __half* __restrict__ Bh, const __half* __restrict__ Bl,
                 float* __restrict__ C, int N,
                 __half* __restrict__ qh, __half* __restrict__ ql,
                 __half* __restrict__ kh, __half* __restrict__ kl,
                 __half* __restrict__ vth, __half* __restrict__ vtl)
{
    extern __shared__ __align__(16) char sm_raw[];
    const int tid  = threadIdx.x;
    const int lane = tid & 31;
    const int wid  = tid >> 5;
    const int wr   = wid & 3;
    const int wc   = wid >> 2;
    const int bm = blockIdx.y * 128, bn = blockIdx.x * 128;
    const uint32_t s0 = smem_u32(sm_raw);

    float acc[2][8][4];
#pragma unroll
    for (int i = 0; i < 2; i++)
#pragma unroll
        for (int j = 0; j < 8; j++)
#pragma unroll
            for (int q = 0; q < 4; q++) acc[i][j][q] = 0.f;

    const int rA_base = wr * 32 + ((lane >> 3) & 1) * 8 + (lane & 7);
    const int cA_half = lane >> 4;
    const int rB_base = wc * 64 + ((lane >> 4) ? 8 : 0) + (lane & 7);
    const int cB_half = (lane >> 3) & 1;

    load_stage(Ah, Al, Bh, Bl, bm, bn, 0, s0, tid);
    CP_COMMIT();

    constexpr int NIT = K_DIM / 32;
    for (int it = 0; it < NIT; it++) {
        if (it + 1 < NIT) {
            load_stage(Ah, Al, Bh, Bl, bm, bn, (it + 1) * 32,
                       s0 + (uint32_t)(((it + 1) & 1) * STG_BYTES), tid);
            CP_COMMIT();
            CP_WAIT1();
        } else {
            CP_WAIT0();
        }
        __syncthreads();

        const uint32_t sa = s0 + (uint32_t)((it & 1) * STG_BYTES);
#pragma unroll
        for (int s = 0; s < 2; s++) {
            uint32_t afh[2][4], afl[2][4], bfh[8][2], bfl[8][2];
            const int cA = s * 2 + cA_half;
            const int cB = s * 2 + cB_half;
#pragma unroll
            for (int mt = 0; mt < 2; mt++) {
                const uint32_t oa = sw_off(rA_base + mt * 16, cA);
                LDSM4(afh[mt][0], afh[mt][1], afh[mt][2], afh[mt][3], sa + oa);
                LDSM4(afl[mt][0], afl[mt][1], afl[mt][2], afl[mt][3], sa + 8192u + oa);
            }
#pragma unroll
            for (int np = 0; np < 4; np++) {
                const uint32_t ob = sw_off(rB_base + np * 16, cB);
                uint32_t t0, t1, t2, t3;
                LDSM4(t0, t1, t2, t3, sa + 16384u + ob);
                bfh[np * 2][0] = t0; bfh[np * 2][1] = t1;
                bfh[np * 2 + 1][0] = t2; bfh[np * 2 + 1][1] = t3;
                LDSM4(t0, t1, t2, t3, sa + 24576u + ob);
                bfl[np * 2][0] = t0; bfl[np * 2][1] = t1;
                bfl[np * 2 + 1][0] = t2; bfl[np * 2 + 1][1] = t3;
            }
#pragma unroll
            for (int mt = 0; mt < 2; mt++)
#pragma unroll
                for (int nt = 0; nt < 8; nt++) {
                    mma16816(acc[mt][nt], afh[mt], bfh[nt]);
                    mma16816(acc[mt][nt], afh[mt], bfl[nt]);
                    mma16816(acc[mt][nt], afl[mt], bfh[nt]);
                }
        }
        __syncthreads();
    }

    if (MODE == 0) {
        // Plain fp32 C epilogue
#pragma unroll
        for (int mt = 0; mt < 2; mt++) {
            const int row = bm + wr * 32 + mt * 16 + (lane >> 2);
#pragma unroll
            for (int nt = 0; nt < 8; nt++) {
                const int col = bn + wc * 64 + nt * 8 + (lane & 3) * 2;
                float* p = C + (size_t)row * N + col;
                float2 v0; v0.x = acc[mt][nt][0]; v0.y = acc[mt][nt][1];
                float2 v1; v1.x = acc[mt][nt][2]; v1.y = acc[mt][nt][3];
                *(float2*)p = v0;
                *(float2*)(p + (size_t)8 * N) = v1;
            }
        }
    } else {
        // Fused QKV epilogue: per-head fp16 hi/lo.
        const int type  = bn >> 10;           // 0=Q, 1=K, 2=V
        const int b     = bm >> 11;
        const int t0    = bm & 2047;
        const int hbase = (bn & 1023) >> 6;   // head for wc=0

        if (type < 2) {
            __half* dh = (type == 0) ? qh : kh;
            __half* dl = (type == 0) ? ql : kl;
            const float scale = (type == 0) ? 0.125f : 1.0f;
            const int bh = b * 16 + hbase + wc;
#pragma unroll
            for (int mt = 0; mt < 2; mt++) {
                const int r0 = t0 + wr * 32 + mt * 16 + (lane >> 2);
                const size_t base0 = ((size_t)bh * T_ + r0) * 64;
                const size_t base1 = ((size_t)bh * T_ + r0 + 8) * 64;
#pragma unroll
                for (int nt = 0; nt < 8; nt++) {
                    const int d = nt * 8 + (lane & 3) * 2;
                    const float v0 = acc[mt][nt][0] * scale;
                    const float v1 = acc[mt][nt][1] * scale;
                    const float v2 = acc[mt][nt][2] * scale;
                    const float v3 = acc[mt][nt][3] * scale;
                    const __half h0 = __float2half_rn(v0), h1 = __float2half_rn(v1);
                    const __half h2 = __float2half_rn(v2), h3 = __float2half_rn(v3);
                    *(uint32_t*)(dh + base0 + d) = pack_h2(h0, h1);
                    *(uint32_t*)(dl + base0 + d) =
                        pack_h2(__float2half_rn(v0 - __half2float(h0)),
                                __float2half_rn(v1 - __half2float(h1)));
                    *(uint32_t*)(dh + base1 + d) = pack_h2(h2, h3);
                    *(uint32_t*)(dl + base1 + d) =
                        pack_h2(__float2half_rn(v2 - __half2float(h2)),
                                __float2half_rn(v3 - __half2float(h3)));
                }
            }
        } else {
            // V: transpose via smem staging, hi pass then lo pass (fits 64KB).
            __half (*arr)[136] = (__half (*)[136])sm_raw;
#pragma unroll
            for (int pass = 0; pass < 2; pass++) {
                __syncthreads();
#pragma unroll
                for (int mt = 0; mt < 2; mt++) {
                    const int tl_ = wr * 32 + mt * 16 + (lane >> 2);
#pragma unroll
                    for (int nt = 0; nt < 8; nt++) {
                        const int drow = wc * 64 + nt * 8 + (lane & 3) * 2;
                        float v0 = acc[mt][nt][0], v1 = acc[mt][nt][1];
                        float v2 = acc[mt][nt][2], v3 = acc[mt][nt][3];
                        __half p0, p1, p2, p3;
                        if (pass == 0) {
                            p0 = __float2half_rn(v0); p1 = __float2half_rn(v1);
                            p2 = __float2half_rn(v2); p3 = __float2half_rn(v3);
                        } else {
                            p0 = __float2half_rn(v0 - __half2float(__float2half_rn(v0)));
                            p1 = __float2half_rn(v1 - __half2float(__float2half_rn(v1)));
                            p2 = __float2half_rn(v2 - __half2float(__float2half_rn(v2)));
                            p3 = __float2half_rn(v3 - __half2float(__float2half_rn(v3)));
                        }
                        arr[drow][tl_]         = p0;
                        arr[drow + 1][tl_]     = p1;
                        arr[drow][tl_ + 8]     = p2;
                        arr[drow + 1][tl_ + 8] = p3;
                    }
                }
                __syncthreads();
                __half* dst = pass ? vtl : vth;
#pragma unroll
                for (int u = 0; u < 8; u++) {
                    const int idx  = tid + u * 256;
                    const int drow = idx >> 4;
                    const int tseg = (idx & 15) * 8;
                    uint4 v = *(uint4*)&arr[drow][tseg];
                    const int head = hbase + (drow >> 6);
                    const int d    = drow & 63;
                    *(uint4*)(dst + ((size_t)(b * 16 + head) * 64 + d) * T_ + t0 + tseg) = v;
                }
            }
        }
    }
}

// ---------------------------------------------------------------------------
// HMMA causal flash attention — exact R8 version (2-stage pipeline).
// ---------------------------------------------------------------------------
#define ATT_STG 32768
#define ATT_DYN (2 * ATT_STG + 1024)

__device__ __forceinline__ void attn_load_stage(
    const __half* __restrict__ kh, const __half* __restrict__ kl,
    const __half* __restrict__ vh, const __half* __restrict__ vl,
    size_t kbase, size_t vbase, int kv0, uint32_t sb, int tid)
{
#pragma unroll
    for (int j = 0; j < 2; j++) {
        const int idx = tid + j * 256;
        const int r = idx >> 3, c = idx & 7;
        const uint32_t so = swk(r, c);
        const size_t ko = kbase + (size_t)(kv0 + r) * 64 + c * 8;
        const size_t vo = vbase + (size_t)r * T_ + kv0 + c * 8;
        CP_ASYNC16(sb +          so, kh + ko);
        CP_ASYNC16(sb + 8192u  + so, kl + ko);
        CP_ASYNC16(sb + 16384u + so, vh + vo);
        CP_ASYNC16(sb + 24576u + so, vl + vo);
    }
}

__global__ __launch_bounds__(256)
void attn_mma(const __half* __restrict__ qh_g, const __half* __restrict__ ql_g,
              const __half* __restrict__ kh_g, const __half* __restrict__ kl_g,
              const __half* __restrict__ vh_g, const __half* __restrict__ vl_g,
              __half* __restrict__ oh_g, __half* __restrict__ ol_g)
{
    extern __shared__ __align__(16) char smraw[];
    const uint32_t s0r = smem_u32(smraw);
    const uint32_t s0  = (s0r + 1023u) & ~1023u;

    const int tid = threadIdx.x, lane = tid & 31, w = tid >> 5;
    const int qb = blockIdx.x, bh = blockIdx.y;
    const int b = bh >> 4, h = bh & 15;
    const int qw  = qb * 128 + w * 16;
    const int qr0 = qw + (lane >> 2);

    uint32_t qfh[4][4], qfl[4][4];
    {
        const size_t base = (size_t)bh * T_ * 64;
        const __half* qp = qh_g + base;
        const __half* lp = ql_g + base;
        const int klo = (lane & 3) << 1;
        const size_t r0o = (size_t)qr0 * 64, r1o = (size_t)(qr0 + 8) * 64;
#pragma unroll
        for (int kd = 0; kd < 4; kd++) {
            const int kk = kd * 16 + klo;
            qfh[kd][0] = *(const uint32_t*)(qp + r0o + kk);
            qfh[kd][1] = *(const uint32_t*)(qp + r1o + kk);
            qfh[kd][2] = *(const uint32_t*)(qp + r0o + kk + 8);
            qfh[kd][3] = *(const uint32_t*)(qp + r1o + kk + 8);
            qfl[kd][0] = *(const uint32_t*)(lp + r0o + kk);
            qfl[kd][1] = *(const uint32_t*)(lp + r1o + kk);
            qfl[kd][2] = *(const uint32_t*)(lp + r0o + kk + 8);
            qfl[kd][3] = *(const uint32_t*)(lp + r1o + kk + 8);
        }
    }

    float accO[8][4];
#pragma unroll
    for (int i = 0; i < 8; i++)
#pragma unroll
        for (int j = 0; j < 4; j++) accO[i][j] = 0.f;
    float m0 = -1e30f, m1 = -1e30f, l0 = 0.f, l1 = 0.f;

    const size_t kbase = (size_t)bh * T_ * 64;
    const size_t vbase = (size_t)bh * 64 * T_;
    const int ntk = 2 * (qb + 1);

    const int bRow = ((lane >> 4) << 3) | (lane & 7);
    const int bSel = (lane >> 3) & 1;

    attn_load_stage(kh_g, kl_g, vh_g, vl_g, kbase, vbase, 0, s0, tid);
    CP_COMMIT();

    for (int t = 0; t < ntk; t++) {
        if (t + 1 < ntk) {
            attn_load_stage(kh_g, kl_g, vh_g, vl_g, kbase, vbase, (t + 1) * 64,
                            s0 + (uint32_t)(((t + 1) & 1) * ATT_STG), tid);
            CP_COMMIT();
            CP_WAIT1();
        } else {
            CP_WAIT0();
        }
        __syncthreads();

        const uint32_t sb = s0 + (uint32_t)((t & 1) * ATT_STG);
        const int kv0 = t * 64;

        if (kv0 <= qw + 15) {
            // ---- S = Q K^T (split x3) ----
            float s[8][4];
#pragma unroll
            for (int i = 0; i < 8; i++)
#pragma unroll
                for (int j = 0; j < 4; j++) s[i][j] = 0.f;

#pragma unroll
            for (int kd = 0; kd < 4; kd++) {
#pragma unroll
                for (int np = 0; np < 4; np++) {
                    const uint32_t off = swk(np * 16 + bRow, kd * 2 + bSel);
                    uint32_t b0, b1, b2, b3, c0, c1, c2, c3;
                    LDSM4(b0, b1, b2, b3, sb + off);
                    LDSM4(c0, c1, c2, c3, sb + 8192u + off);
                    uint32_t Bh0[2] = {b0, b1}, Bh1[2] = {b2, b3};
                    uint32_t Bl0[2] = {c0, c1}, Bl1[2] = {c2, c3};
                    mma16816(s[2 * np],     qfh[kd], Bh0);
                    mma16816(s[2 * np],     qfl[kd], Bh0);
                    mma16816(s[2 * np],     qfh[kd], Bl0);
                    mma16816(s[2 * np + 1], qfh[kd], Bh1);
                    mma16816(s[2 * np + 1], qfl[kd], Bh1);
                    mma16816(s[2 * np + 1], qfh[kd], Bl1);
                }
            }

            // ---- causal mask ----
            if (kv0 + 63 > qw) {
#pragma unroll
                for (int nt = 0; nt < 8; nt++) {
                    const int col = kv0 + nt * 8 + ((lane & 3) << 1);
                    if (col     > qr0)     s[nt][0] = -1e30f;
                    if (col + 1 > qr0)     s[nt][1] = -1e30f;
                    if (col     > qr0 + 8) s[nt][2] = -1e30f;
                    if (col + 1 > qr0 + 8) s[nt][3] = -1e30f;
                }
            }

            // ---- online softmax ----
            float mx0 = -1e30f, mx1 = -1e30f;
#pragma unroll
            for (int nt = 0; nt < 8; nt++) {
                mx0 = fmaxf(mx0, fmaxf(s[nt][0], s[nt][1]));
                mx1 = fmaxf(mx1, fmaxf(s[nt][2], s[nt][3]));
            }
            mx0 = fmaxf(mx0, __shfl_xor_sync(0xffffffffu, mx0, 1));
            mx0 = fmaxf(mx0, __shfl_xor_sync(0xffffffffu, mx0, 2));
            mx1 = fmaxf(mx1, __shfl_xor_sync(0xffffffffu, mx1, 1));
            mx1 = fmaxf(mx1, __shfl_xor_sync(0xffffffffu, mx1, 2));
            const float mn0 = fmaxf(m0, mx0), mn1 = fmaxf(m1, mx1);
            const float a0 = __expf(m0 - mn0), a1 = __expf(m1 - mn1);
            m0 = mn0; m1 = mn1;
            l0 *= a0;  l1 *= a1;
#pragma unroll
            for (int nt = 0; nt < 8; nt++) {
                accO[nt][0] *= a0; accO[nt][1] *= a0;
                accO[nt][2] *= a1; accO[nt][3] *= a1;
            }

            uint32_t ph[4][4], pl[4][4];
            float sum0 = 0.f, sum1 = 0.f;
#pragma unroll
            for (int nt = 0; nt < 8; nt++) {
                const float p0 = __expf(s[nt][0] - m0);
                const float p1 = __expf(s[nt][1] - m0);
                const float p2 = __expf(s[nt][2] - m1);
                const float p3 = __expf(s[nt][3] - m1);
                sum0 += p0 + p1; sum1 += p2 + p3;
                const __half h0 = __float2half_rn(p0), h1 = __float2half_rn(p1);
                const __half h2 = __float2half_rn(p2), h3 = __float2half_rn(p3);
                const int kt = nt >> 1, rg = (nt & 1) * 2;
                ph[kt][rg]     = pack_h2(h0, h1);
                ph[kt][rg + 1] = pack_h2(h2, h3);
                pl[kt][rg]     = pack_h2(__float2half_rn(p0 - __half2float(h0)),
                                         __float2half_rn(p1 - __half2float(h1)));
                pl[kt][rg + 1] = pack_h2(__float2half_rn(p2 - __half2float(h2)),
                                         __float2half_rn(p3 - __half2float(h3)));
            }
            sum0 += __shfl_xor_sync(0xffffffffu, sum0, 1);
            sum0 += __shfl_xor_sync(0xffffffffu, sum0, 2);
            sum1 += __shfl_xor_sync(0xffffffffu, sum1, 1);
            sum1 += __shfl_xor_sync(0xffffffffu, sum1, 2);
            l0 += sum0; l1 += sum1;

            // ---- O += P V (split x3) ----
#pragma unroll
            for (int kt = 0; kt < 4; kt++) {
#pragma unroll
                for (int np = 0; np < 4; np++) {
                    const uint32_t off = swk(np * 16 + bRow, kt * 2 + bSel);
                    uint32_t v0, v1, v2, v3, u0, u1, u2, u3;
                    LDSM4(v0, v1, v2, v3, sb + 16384u + off);
                    LDSM4(u0, u1, u2, u3, sb + 24576u + off);
                    uint32_t Vh0[2] = {v0, v1}, Vh1[2] = {v2, v3};
                    uint32_t Vl0[2] = {u0, u1}, Vl1[2] = {u2, u3};
                    mma16816(accO[2 * np],     ph[kt], Vh0);
                    mma16816(accO[2 * np],     pl[kt], Vh0);
                    mma16816(accO[2 * np],     ph[kt], Vl0);
                    mma16816(accO[2 * np + 1], ph[kt], Vh1);
                    mma16816(accO[2 * np + 1], pl[kt], Vh1);
                    mma16816(accO[2 * np + 1], ph[kt], Vl1);
                }
            }
        }
        __syncthreads();
    }

    // ---- epilogue ----
    const float inv0 = 1.f / l0, inv1 = 1.f / l1;
    const size_t row0 = (size_t)(b * T_ + qr0) * C_ + h * 64;
    const size_t row1 = (size_t)(b * T_ + qr0 + 8) * C_ + h * 64;
#pragma unroll
    for (int nt = 0; nt < 8; nt++) {
        const int col = nt * 8 + ((lane & 3) << 1);
        const float o0 = accO[nt][0] * inv0, o1 = accO[nt][1] * inv0;
        const float o2 = accO[nt][2] * inv1, o3 = accO[nt][3] * inv1;
        const __half h0 = __float2half_rn(o0), h1 = __float2half_rn(o1);
        const __half h2 = __float2half_rn(o2), h3 = __float2half_rn(o3);
        *(uint32_t*)(oh_g + row0 + col) = pack_h2(h0, h1);
        *(uint32_t*)(ol_g + row0 + col) = pack_h2(__float2half_rn(o0 - __half2float(h0)),
                                                  __float2half_rn(o1 - __half2float(h1)));
        *(uint32_t*)(oh_g + row1 + col) = pack_h2(h2, h3);
        *(uint32_t*)(ol_g + row1 + col) = pack_h2(__float2half_rn(o2 - __half2float(h2)),
                                                  __float2half_rn(o3 - __half2float(h3)));
    }
}

// ---------------------------------------------------------------------------
// kernel_launch
// ---------------------------------------------------------------------------
extern "C" void kernel_launch(void* const* d_in, const int* in_sizes, int n_in,
                              void* d_out, int out_size)
{
    (void)in_sizes; (void)n_in; (void)out_size;
    const float* x    = (const float*)d_in[0];
    const float* Wqkv = (const float*)d_in[1];
    const float* Wout = (const float*)d_in[2];
    float* out = (float*)d_out;

    __half *ah, *al, *wqh, *wql, *woh, *wol, *qh, *ql, *kh, *kl, *vth, *vtl;
    cudaGetSymbolAddress((void**)&ah,  g_ah);
    cudaGetSymbolAddress((void**)&al,  g_al);
    cudaGetSymbolAddress((void**)&wqh, g_wqh);
    cudaGetSymbolAddress((void**)&wql, g_wql);
    cudaGetSymbolAddress((void**)&woh, g_woh);
    cudaGetSymbolAddress((void**)&wol, g_wol);
    cudaGetSymbolAddress((void**)&qh,  g_qh);
    cudaGetSymbolAddress((void**)&ql,  g_ql);
    cudaGetSymbolAddress((void**)&kh,  g_kh);
    cudaGetSymbolAddress((void**)&kl,  g_kl);
    cudaGetSymbolAddress((void**)&vth, g_vth);
    cudaGetSymbolAddress((void**)&vtl, g_vtl);

    cudaFuncSetAttribute(hmma_gemm_t<0>, cudaFuncAttributeMaxDynamicSharedMemorySize, HG_DYN);
    cudaFuncSetAttribute(hmma_gemm_t<1>, cudaFuncAttributeMaxDynamicSharedMemorySize, HG_DYN);
    cudaFuncSetAttribute(attn_mma,       cudaFuncAttributeMaxDynamicSharedMemorySize, ATT_DYN);

    const int n_elems4 = (M_ROWS * K_DIM) / 4;

    // 0) Split-convert x and transposed weights to fp16 hi/lo
    conv_split<<<n_elems4 / 256, 256>>>((const float4*)x, (__half2*)ah, (__half2*)al);
    transpose_split<<<dim3(QKV_N / 32, K_DIM / 32), 256>>>(Wqkv, wqh, wql, K_DIM, QKV_N);
    transpose_split<<<dim3(C_ / 32, K_DIM / 32), 256>>>(Wout, woh, wol, K_DIM, C_);

    // 1) QKV projection with fused per-head split/transpose epilogue
    hmma_gemm_t<1><<<dim3(QKV_N / 128, M_ROWS / 128), 256, HG_DYN>>>(
        ah, al, wqh, wql, nullptr, QKV_N, qh, ql, kh, kl, vth, vtl);

    // 2) Causal attention on tensor cores; O written as fp16 hi/lo into ah/al
    attn_mma<<<dim3(T_ / 128, B_ * H_), 256, ATT_DYN>>>(qh, ql, kh, kl, vth, vtl, ah, al);

    // 3) Output projection (plain fp32 epilogue)
    hmma_gemm_t<0><<<dim3(C_ / 128, M_ROWS / 128), 256, HG_DYN>>>(
        ah, al, woh, wol, out, C_, nullptr, nullptr, nullptr, nullptr, nullptr, nullptr);
}

// round 13
// speedup vs baseline: 1.9296x; 1.2982x over previous
#include <cuda_runtime.h>
#include <cuda_fp16.h>
#include <cstdint>

// Problem constants
#define B_  4
#define T_  2048
#define C_  1024
#define H_  16
#define DH_ 64
#define M_ROWS (B_ * T_)      // 8192
#define QKV_N  (3 * C_)       // 3072
#define K_DIM  1024

// ---------------------------------------------------------------------------
// Device scratch
// ---------------------------------------------------------------------------
__device__ __half g_ah[(size_t)M_ROWS * K_DIM];        // A hi (x, later O)
__device__ __half g_al[(size_t)M_ROWS * K_DIM];        // A lo
__device__ __half g_wqh[(size_t)QKV_N * K_DIM];        // W_qkv^T fp16
__device__ __half g_woh[(size_t)C_ * K_DIM];           // W_out^T fp16
// per-head fp16: q split hi/lo [bh][T][64]; k single [bh][T][64]; v^T single [bh][64][T]
__device__ __half g_qh[(size_t)B_ * H_ * T_ * DH_];
__device__ __half g_ql[(size_t)B_ * H_ * T_ * DH_];
__device__ __half g_kh[(size_t)B_ * H_ * T_ * DH_];
__device__ __half g_vth[(size_t)B_ * H_ * DH_ * T_];

// ---------------------------------------------------------------------------
// Portable PTX helpers
// ---------------------------------------------------------------------------
__device__ __forceinline__ uint32_t smem_u32(const void* p) {
    uint32_t a;
    asm("{ .reg .u64 t; cvta.to.shared.u64 t, %1; cvt.u32.u64 %0, t; }" : "=r"(a) : "l"(p));
    return a;
}
#define CP_ASYNC16(dst, src) \
    asm volatile("cp.async.cg.shared.global [%0], [%1], 16;" :: "r"(dst), "l"(src))
#define CP_COMMIT() asm volatile("cp.async.commit_group;" ::: "memory")
#define CP_WAIT1()  asm volatile("cp.async.wait_group 1;" ::: "memory")
#define CP_WAIT0()  asm volatile("cp.async.wait_group 0;" ::: "memory")
#define LDSM4(r0, r1, r2, r3, addr) \
    asm volatile("ldmatrix.sync.aligned.m8n8.x4.shared.b16 {%0,%1,%2,%3}, [%4];" \
                 : "=r"(r0), "=r"(r1), "=r"(r2), "=r"(r3) : "r"(addr))

__device__ __forceinline__ void mma16816(float* c, const uint32_t* a, const uint32_t* b) {
    asm volatile(
        "mma.sync.aligned.m16n8k16.row.col.f32.f16.f16.f32 "
        "{%0,%1,%2,%3},{%4,%5,%6,%7},{%8,%9},{%0,%1,%2,%3};"
        : "+f"(c[0]), "+f"(c[1]), "+f"(c[2]), "+f"(c[3])
        : "r"(a[0]), "r"(a[1]), "r"(a[2]), "r"(a[3]), "r"(b[0]), "r"(b[1]));
}

// Swizzle for 64B-row tiles (GEMM: [128 rows x 4 chunks])
__device__ __forceinline__ uint32_t sw_off(int r, int c) {
    return (uint32_t)((r << 2) | (c ^ ((r >> 1) & 3))) << 4;
}
// Swizzle for 128B-row tiles (attention: [64 rows x 8 chunks])
__device__ __forceinline__ uint32_t swk(int r, int c) {
    return (uint32_t)((r << 3) | (c ^ (r & 7))) << 4;
}
__device__ __forceinline__ uint32_t pack_h2(__half a, __half b) {
    __half2 h = __halves2half2(a, b);
    return *(uint32_t*)&h;
}

// ---------------------------------------------------------------------------
// Conversion kernels
// ---------------------------------------------------------------------------
__global__ __launch_bounds__(256)
void conv_split(const float4* __restrict__ src, __half2* __restrict__ hi,
                __half2* __restrict__ lo)
{
    const int i = blockIdx.x * 256 + threadIdx.x;
    float4 v = src[i];
    __half h0 = __float2half_rn(v.x), h1 = __float2half_rn(v.y);
    __half h2 = __float2half_rn(v.z), h3 = __float2half_rn(v.w);
    __half l0 = __float2half_rn(v.x - __half2float(h0));
    __half l1 = __float2half_rn(v.y - __half2float(h1));
    __half l2 = __float2half_rn(v.z - __half2float(h2));
    __half l3 = __float2half_rn(v.w - __half2float(h3));
    hi[2 * i]     = __halves2half2(h0, h1);
    hi[2 * i + 1] = __halves2half2(h2, h3);
    lo[2 * i]     = __halves2half2(l0, l1);
    lo[2 * i + 1] = __halves2half2(l2, l3);
}

// W[K,N] -> W^T fp16 [N,K] (single precision level)
__global__ __launch_bounds__(256)
void transpose_h(const float* __restrict__ W, __half* __restrict__ Th, int K, int N)
{
    __shared__ float tile[32][33];
    const int n0 = blockIdx.x * 32, k0 = blockIdx.y * 32;
    const int tx = threadIdx.x & 31, ty = threadIdx.x >> 5;
#pragma unroll
    for (int j = 0; j < 32; j += 8)
        tile[ty + j][tx] = W[(size_t)(k0 + ty + j) * N + n0 + tx];
    __syncthreads();
#pragma unroll
    for (int j = 0; j < 32; j += 8)
        Th[(size_t)(n0 + ty + j) * K + k0 + tx] = __float2half_rn(tile[tx][ty + j]);
}

// ---------------------------------------------------------------------------
// HMMA GEMM: C = (Ah+Al) @ Bh^T — A split fp16, B single fp16, fp32 accum.
// 128x128 CTA tile, BK=32, 2-stage cp.async pipeline (R8-proven structure).
// MODE 0: fp32 C.  MODE 1: fused QKV epilogue.
// ---------------------------------------------------------------------------
#define STG_BYTES 24576               // Ah 8K | Al 8K | Bh 8K
#define HG_DYN    (2 * STG_BYTES)

__device__ __forceinline__ void load_stage(
    const __half* __restrict__ Ah, const __half* __restrict__ Al,
    const __half* __restrict__ Bh,
    int bm, int bn, int k0, uint32_t sbase, int tid)
{
#pragma unroll
    for (int i = 0; i < 2; i++) {
        const int idx = tid + i * 256;
        const int r = idx >> 2;
        const int c = idx & 3;
        const uint32_t so = sw_off(r, c);
        const size_t goA = (size_t)(bm + r) * K_DIM + k0 + c * 8;
        const size_t goB = (size_t)(bn + r) * K_DIM + k0 + c * 8;
        CP_ASYNC16(sbase +          so, Ah + goA);
        CP_ASYNC16(sbase + 8192u  + so, Al + goA);
        CP_ASYNC16(sbase + 16384u + so, Bh + goB);
    }
}

template<int MODE>
__global__ __launch_bounds__(256)
void hmma_gemm_t(const __half* __restrict__ Ah, const __half* __restrict__ Al,
                 const __half* __restrict__ Bh,
                 float* __restrict__ C, int N,
                 __half* __restrict__ qh, __half* __restrict__ ql,
                 __half* __restrict__ kh, __half* __restrict__ vth)
{
    extern __shared__ __align__(16) char sm_raw[];
    const int tid  = threadIdx.x;
    const int lane = tid & 31;
    const int wid  = tid >> 5;
    const int wr   = wid & 3;
    const int wc   = wid >> 2;
    const int bm = blockIdx.y * 128, bn = blockIdx.x * 128;
    const uint32_t s0 = smem_u32(sm_raw);

    float acc[2][8][4];
#pragma unroll
    for (int i = 0; i < 2; i++)
#pragma unroll
        for (int j = 0; j < 8; j++)
#pragma unroll
            for (int q = 0; q < 4; q++) acc[i][j][q] = 0.f;

    const int rA_base = wr * 32 + ((lane >> 3) & 1) * 8 + (lane & 7);
    const int cA_half = lane >> 4;
    const int rB_base = wc * 64 + ((lane >> 4) ? 8 : 0) + (lane & 7);
    const int cB_half = (lane >> 3) & 1;

    load_stage(Ah, Al, Bh, bm, bn, 0, s0, tid);
    CP_COMMIT();

    constexpr int NIT = K_DIM / 32;
    for (int it = 0; it < NIT; it++) {
        if (it + 1 < NIT) {
            load_stage(Ah, Al, Bh, bm, bn, (it + 1) * 32,
                       s0 + (uint32_t)(((it + 1) & 1) * STG_BYTES), tid);
            CP_COMMIT();
            CP_WAIT1();
        } else {
            CP_WAIT0();
        }
        __syncthreads();

        const uint32_t sa = s0 + (uint32_t)((it & 1) * STG_BYTES);
#pragma unroll
        for (int s = 0; s < 2; s++) {
            uint32_t afh[2][4], afl[2][4], bfh[8][2];
            const int cA = s * 2 + cA_half;
            const int cB = s * 2 + cB_half;
#pragma unroll
            for (int mt = 0; mt < 2; mt++) {
                const uint32_t oa = sw_off(rA_base + mt * 16, cA);
                LDSM4(afh[mt][0], afh[mt][1], afh[mt][2], afh[mt][3], sa + oa);
                LDSM4(afl[mt][0], afl[mt][1], afl[mt][2], afl[mt][3], sa + 8192u + oa);
            }
#pragma unroll
            for (int np = 0; np < 4; np++) {
                const uint32_t ob = sw_off(rB_base + np * 16, cB);
                uint32_t t0, t1, t2, t3;
                LDSM4(t0, t1, t2, t3, sa + 16384u + ob);
                bfh[np * 2][0] = t0; bfh[np * 2][1] = t1;
                bfh[np * 2 + 1][0] = t2; bfh[np * 2 + 1][1] = t3;
            }
#pragma unroll
            for (int mt = 0; mt < 2; mt++)
#pragma unroll
                for (int nt = 0; nt < 8; nt++) {
                    mma16816(acc[mt][nt], afh[mt], bfh[nt]);   // a_hi * b
                    mma16816(acc[mt][nt], afl[mt], bfh[nt]);   // a_lo * b
                }
        }
        __syncthreads();
    }

    if (MODE == 0) {
#pragma unroll
        for (int mt = 0; mt < 2; mt++) {
            const int row = bm + wr * 32 + mt * 16 + (lane >> 2);
#pragma unroll
            for (int nt = 0; nt < 8; nt++) {
                const int col = bn + wc * 64 + nt * 8 + (lane & 3) * 2;
                float* p = C + (size_t)row * N + col;
                float2 v0; v0.x = acc[mt][nt][0]; v0.y = acc[mt][nt][1];
                float2 v1; v1.x = acc[mt][nt][2]; v1.y = acc[mt][nt][3];
                *(float2*)p = v0;
                *(float2*)(p + (size_t)8 * N) = v1;
            }
        }
    } else {
        // Fused QKV epilogue.
        const int type  = bn >> 10;           // 0=Q, 1=K, 2=V
        const int b     = bm >> 11;
        const int t0    = bm & 2047;
        const int hbase = (bn & 1023) >> 6;

        if (type < 2) {
            const float scale = (type == 0) ? 0.125f : 1.0f;
            const int bh = b * 16 + hbase + wc;
#pragma unroll
            for (int mt = 0; mt < 2; mt++) {
                const int r0 = t0 + wr * 32 + mt * 16 + (lane >> 2);
                const size_t base0 = ((size_t)bh * T_ + r0) * 64;
                const size_t base1 = ((size_t)bh * T_ + r0 + 8) * 64;
#pragma unroll
                for (int nt = 0; nt < 8; nt++) {
                    const int d = nt * 8 + (lane & 3) * 2;
                    const float v0 = acc[mt][nt][0] * scale;
                    const float v1 = acc[mt][nt][1] * scale;
                    const float v2 = acc[mt][nt][2] * scale;
                    const float v3 = acc[mt][nt][3] * scale;
                    const __half h0 = __float2half_rn(v0), h1 = __float2half_rn(v1);
                    const __half h2 = __float2half_rn(v2), h3 = __float2half_rn(v3);
                    if (type == 0) {
                        *(uint32_t*)(qh + base0 + d) = pack_h2(h0, h1);
                        *(uint32_t*)(ql + base0 + d) =
                            pack_h2(__float2half_rn(v0 - __half2float(h0)),
                                    __float2half_rn(v1 - __half2float(h1)));
                        *(uint32_t*)(qh + base1 + d) = pack_h2(h2, h3);
                        *(uint32_t*)(ql + base1 + d) =
                            pack_h2(__float2half_rn(v2 - __half2float(h2)),
                                    __float2half_rn(v3 - __half2float(h3)));
                    } else {
                        *(uint32_t*)(kh + base0 + d) = pack_h2(h0, h1);
                        *(uint32_t*)(kh + base1 + d) = pack_h2(h2, h3);
                    }
                }
            }
        } else {
            // V: single fp16, transpose via smem staging.
            __half (*arr)[136] = (__half (*)[136])sm_raw;
            __syncthreads();
#pragma unroll
            for (int mt = 0; mt < 2; mt++) {
                const int tl_ = wr * 32 + mt * 16 + (lane >> 2);
#pragma unroll
                for (int nt = 0; nt < 8; nt++) {
                    const int drow = wc * 64 + nt * 8 + (lane & 3) * 2;
                    arr[drow][tl_]         = __float2half_rn(acc[mt][nt][0]);
                    arr[drow + 1][tl_]     = __float2half_rn(acc[mt][nt][1]);
                    arr[drow][tl_ + 8]     = __float2half_rn(acc[mt][nt][2]);
                    arr[drow + 1][tl_ + 8] = __float2half_rn(acc[mt][nt][3]);
                }
            }
            __syncthreads();
#pragma unroll
            for (int u = 0; u < 8; u++) {
                const int idx  = tid + u * 256;
                const int drow = idx >> 4;
                const int tseg = (idx & 15) * 8;
                uint4 v = *(uint4*)&arr[drow][tseg];
                const int head = hbase + (drow >> 6);
                const int d    = drow & 63;
                *(uint4*)(vth + ((size_t)(b * 16 + head) * 64 + d) * T_ + t0 + tseg) = v;
            }
        }
    }
}

// ---------------------------------------------------------------------------
// HMMA causal flash attention — K and V single fp16, Q and P split.
// ---------------------------------------------------------------------------
#define ATT_STG 16384                 // Kh 8K | Vh 8K
#define ATT_DYN (2 * ATT_STG + 1024)

__device__ __forceinline__ void attn_load_stage(
    const __half* __restrict__ kh, const __half* __restrict__ vh,
    size_t kbase, size_t vbase, int kv0, uint32_t sb, int tid)
{
#pragma unroll
    for (int j = 0; j < 2; j++) {
        const int idx = tid + j * 256;
        const int r = idx >> 3, c = idx & 7;
        const uint32_t so = swk(r, c);
        CP_ASYNC16(sb +         so, kh + kbase + (size_t)(kv0 + r) * 64 + c * 8);
        CP_ASYNC16(sb + 8192u + so, vh + vbase + (size_t)r * T_ + kv0 + c * 8);
    }
}

__global__ __launch_bounds__(256)
void attn_mma(const __half* __restrict__ qh_g, const __half* __restrict__ ql_g,
              const __half* __restrict__ kh_g, const __half* __restrict__ vh_g,
              __half* __restrict__ oh_g, __half* __restrict__ ol_g)
{
    extern __shared__ __align__(16) char smraw[];
    const uint32_t s0r = smem_u32(smraw);
    const uint32_t s0  = (s0r + 1023u) & ~1023u;

    const int tid = threadIdx.x, lane = tid & 31, w = tid >> 5;
    const int qb = blockIdx.x, bh = blockIdx.y;
    const int b = bh >> 4, h = bh & 15;
    const int qw  = qb * 128 + w * 16;
    const int qr0 = qw + (lane >> 2);

    uint32_t qfh[4][4], qfl[4][4];
    {
        const size_t base = (size_t)bh * T_ * 64;
        const __half* qp = qh_g + base;
        const __half* lp = ql_g + base;
        const int klo = (lane & 3) << 1;
        const size_t r0o = (size_t)qr0 * 64, r1o = (size_t)(qr0 + 8) * 64;
#pragma unroll
        for (int kd = 0; kd < 4; kd++) {
            const int kk = kd * 16 + klo;
            qfh[kd][0] = *(const uint32_t*)(qp + r0o + kk);
            qfh[kd][1] = *(const uint32_t*)(qp + r1o + kk);
            qfh[kd][2] = *(const uint32_t*)(qp + r0o + kk + 8);
            qfh[kd][3] = *(const uint32_t*)(qp + r1o + kk + 8);
            qfl[kd][0] = *(const uint32_t*)(lp + r0o + kk);
            qfl[kd][1] = *(const uint32_t*)(lp + r1o + kk);
            qfl[kd][2] = *(const uint32_t*)(lp + r0o + kk + 8);
            qfl[kd][3] = *(const uint32_t*)(lp + r1o + kk + 8);
        }
    }

    float accO[8][4];
#pragma unroll
    for (int i = 0; i < 8; i++)
#pragma unroll
        for (int j = 0; j < 4; j++) accO[i][j] = 0.f;
    float m0 = -1e30f, m1 = -1e30f, l0 = 0.f, l1 = 0.f;

    const size_t kbase = (size_t)bh * T_ * 64;
    const size_t vbase = (size_t)bh * 64 * T_;
    const int ntk = 2 * (qb + 1);

    const int bRow = ((lane >> 4) << 3) | (lane & 7);
    const int bSel = (lane >> 3) & 1;

    attn_load_stage(kh_g, vh_g, kbase, vbase, 0, s0, tid);
    CP_COMMIT();

    for (int t = 0; t < ntk; t++) {
        if (t + 1 < ntk) {
            attn_load_stage(kh_g, vh_g, kbase, vbase, (t + 1) * 64,
                            s0 + (uint32_t)(((t + 1) & 1) * ATT_STG), tid);
            CP_COMMIT();
            CP_WAIT1();
        } else {
            CP_WAIT0();
        }
        __syncthreads();

        const uint32_t sb = s0 + (uint32_t)((t & 1) * ATT_STG);
        const int kv0 = t * 64;

        if (kv0 <= qw + 15) {
            // ---- S = (Qh+Ql) K^T ----
            float s[8][4];
#pragma unroll
            for (int i = 0; i < 8; i++)
#pragma unroll
                for (int j = 0; j < 4; j++) s[i][j] = 0.f;

#pragma unroll
            for (int kd = 0; kd < 4; kd++) {
#pragma unroll
                for (int np = 0; np < 4; np++) {
                    const uint32_t off = swk(np * 16 + bRow, kd * 2 + bSel);
                    uint32_t b0, b1, b2, b3;
                    LDSM4(b0, b1, b2, b3, sb + off);
                    uint32_t Bh0[2] = {b0, b1}, Bh1[2] = {b2, b3};
                    mma16816(s[2 * np],     qfh[kd], Bh0);
                    mma16816(s[2 * np],     qfl[kd], Bh0);
                    mma16816(s[2 * np + 1], qfh[kd], Bh1);
                    mma16816(s[2 * np + 1], qfl[kd], Bh1);
                }
            }

            // ---- causal mask ----
            if (kv0 + 63 > qw) {
#pragma unroll
                for (int nt = 0; nt < 8; nt++) {
                    const int col = kv0 + nt * 8 + ((lane & 3) << 1);
                    if (col     > qr0)     s[nt][0] = -1e30f;
                    if (col + 1 > qr0)     s[nt][1] = -1e30f;
                    if (col     > qr0 + 8) s[nt][2] = -1e30f;
                    if (col + 1 > qr0 + 8) s[nt][3] = -1e30f;
                }
            }

            // ---- online softmax ----
            float mx0 = -1e30f, mx1 = -1e30f;
#pragma unroll
            for (int nt = 0; nt < 8; nt++) {
                mx0 = fmaxf(mx0, fmaxf(s[nt][0], s[nt][1]));
                mx1 = fmaxf(mx1, fmaxf(s[nt][2], s[nt][3]));
            }
            mx0 = fmaxf(mx0, __shfl_xor_sync(0xffffffffu, mx0, 1));
            mx0 = fmaxf(mx0, __shfl_xor_sync(0xffffffffu, mx0, 2));
            mx1 = fmaxf(mx1, __shfl_xor_sync(0xffffffffu, mx1, 1));
            mx1 = fmaxf(mx1, __shfl_xor_sync(0xffffffffu, mx1, 2));
            const float mn0 = fmaxf(m0, mx0), mn1 = fmaxf(m1, mx1);
            const float a0 = __expf(m0 - mn0), a1 = __expf(m1 - mn1);
            m0 = mn0; m1 = mn1;
            l0 *= a0;  l1 *= a1;
#pragma unroll
            for (int nt = 0; nt < 8; nt++) {
                accO[nt][0] *= a0; accO[nt][1] *= a0;
                accO[nt][2] *= a1; accO[nt][3] *= a1;
            }

            uint32_t ph[4][4], pl[4][4];
            float sum0 = 0.f, sum1 = 0.f;
#pragma unroll
            for (int nt = 0; nt < 8; nt++) {
                const float p0 = __expf(s[nt][0] - m0);
                const float p1 = __expf(s[nt][1] - m0);
                const float p2 = __expf(s[nt][2] - m1);
                const float p3 = __expf(s[nt][3] - m1);
                sum0 += p0 + p1; sum1 += p2 + p3;
                const __half h0 = __float2half_rn(p0), h1 = __float2half_rn(p1);
                const __half h2 = __float2half_rn(p2), h3 = __float2half_rn(p3);
                const int kt = nt >> 1, rg = (nt & 1) * 2;
                ph[kt][rg]     = pack_h2(h0, h1);
                ph[kt][rg + 1] = pack_h2(h2, h3);
                pl[kt][rg]     = pack_h2(__float2half_rn(p0 - __half2float(h0)),
                                         __float2half_rn(p1 - __half2float(h1)));
                pl[kt][rg + 1] = pack_h2(__float2half_rn(p2 - __half2float(h2)),
                                         __float2half_rn(p3 - __half2float(h3)));
            }
            sum0 += __shfl_xor_sync(0xffffffffu, sum0, 1);
            sum0 += __shfl_xor_sync(0xffffffffu, sum0, 2);
            sum1 += __shfl_xor_sync(0xffffffffu, sum1, 1);
            sum1 += __shfl_xor_sync(0xffffffffu, sum1, 2);
            l0 += sum0; l1 += sum1;

            // ---- O += (Ph+Pl) V ----
#pragma unroll
            for (int kt = 0; kt < 4; kt++) {
#pragma unroll
                for (int np = 0; np < 4; np++) {
                    const uint32_t off = swk(np * 16 + bRow, kt * 2 + bSel);
                    uint32_t v0, v1, v2, v3;
                    LDSM4(v0, v1, v2, v3, sb + 8192u + off);
                    uint32_t Vh0[2] = {v0, v1}, Vh1[2] = {v2, v3};
                    mma16816(accO[2 * np],     ph[kt], Vh0);
                    mma16816(accO[2 * np],     pl[kt], Vh0);
                    mma16816(accO[2 * np + 1], ph[kt], Vh1);
                    mma16816(accO[2 * np + 1], pl[kt], Vh1);
                }
            }
        }
        __syncthreads();
    }

    // ---- epilogue: normalize, split to fp16 hi/lo for out-proj ----
    const float inv0 = 1.f / l0, inv1 = 1.f / l1;
    const size_t row0 = (size_t)(b * T_ + qr0) * C_ + h * 64;
    const size_t row1 = (size_t)(b * T_ + qr0 + 8) * C_ + h * 64;
#pragma unroll
    for (int nt = 0; nt < 8; nt++) {
        const int col = nt * 8 + ((lane & 3) << 1);
        const float o0 = accO[nt][0] * inv0, o1 = accO[nt][1] * inv0;
        const float o2 = accO[nt][2] * inv1, o3 = accO[nt][3] * inv1;
        const __half h0 = __float2half_rn(o0), h1 = __float2half_rn(o1);
        const __half h2 = __float2half_rn(o2), h3 = __float2half_rn(o3);
        *(uint32_t*)(oh_g + row0 + col) = pack_h2(h0, h1);
        *(uint32_t*)(ol_g + row0 + col) = pack_h2(__float2half_rn(o0 - __half2float(h0)),
                                                  __float2half_rn(o1 - __half2float(h1)));
        *(uint32_t*)(oh_g + row1 + col) = pack_h2(h2, h3);
        *(uint32_t*)(ol_g + row1 + col) = pack_h2(__float2half_rn(o2 - __half2float(h2)),
                                                  __float2half_rn(o3 - __half2float(h3)));
    }
}

// ---------------------------------------------------------------------------
// kernel_launch
// ---------------------------------------------------------------------------
extern "C" void kernel_launch(void* const* d_in, const int* in_sizes, int n_in,
                              void* d_out, int out_size)
{
    (void)in_sizes; (void)n_in; (void)out_size;
    const float* x    = (const float*)d_in[0];
    const float* Wqkv = (const float*)d_in[1];
    const float* Wout = (const float*)d_in[2];
    float* out = (float*)d_out;

    __half *ah, *al, *wqh, *woh, *qh, *ql, *kh, *vth;
    cudaGetSymbolAddress((void**)&ah,  g_ah);
    cudaGetSymbolAddress((void**)&al,  g_al);
    cudaGetSymbolAddress((void**)&wqh, g_wqh);
    cudaGetSymbolAddress((void**)&woh, g_woh);
    cudaGetSymbolAddress((void**)&qh,  g_qh);
    cudaGetSymbolAddress((void**)&ql,  g_ql);
    cudaGetSymbolAddress((void**)&kh,  g_kh);
    cudaGetSymbolAddress((void**)&vth, g_vth);

    cudaFuncSetAttribute(hmma_gemm_t<0>, cudaFuncAttributeMaxDynamicSharedMemorySize, HG_DYN);
    cudaFuncSetAttribute(hmma_gemm_t<1>, cudaFuncAttributeMaxDynamicSharedMemorySize, HG_DYN);
    cudaFuncSetAttribute(attn_mma,       cudaFuncAttributeMaxDynamicSharedMemorySize, ATT_DYN);

    const int n_elems4 = (M_ROWS * K_DIM) / 4;

    // 0) Split-convert x (hi/lo); weights to single fp16 transposed
    conv_split<<<n_elems4 / 256, 256>>>((const float4*)x, (__half2*)ah, (__half2*)al);
    transpose_h<<<dim3(QKV_N / 32, K_DIM / 32), 256>>>(Wqkv, wqh, K_DIM, QKV_N);
    transpose_h<<<dim3(C_ / 32, K_DIM / 32), 256>>>(Wout, woh, K_DIM, C_);

    // 1) QKV projection (A split, B single) with fused per-head epilogue
    hmma_gemm_t<1><<<dim3(QKV_N / 128, M_ROWS / 128), 256, HG_DYN>>>(
        ah, al, wqh, nullptr, QKV_N, qh, ql, kh, vth);

    // 2) Causal attention; O written as fp16 hi/lo into ah/al
    attn_mma<<<dim3(T_ / 128, B_ * H_), 256, ATT_DYN>>>(qh, ql, kh, vth, ah, al);

    // 3) Output projection (A = O split, B single)
    hmma_gemm_t<0><<<dim3(C_ / 128, M_ROWS / 128), 256, HG_DYN>>>(
        ah, al, woh, out, C_, nullptr, nullptr, nullptr, nullptr);
}